// round 14
// baseline (speedup 1.0000x reference)
#include <cuda_runtime.h>
#include <cuda_bf16.h>
#include <cstdint>

#define KBLK   8
#define IDIM   96
#define ODIM   96
#define XYTOT  65160
#define XYH    (XYTOT/2)
#define XYT    32
#define NTHR   256
#define NCON   192
#define NTILES 2037            // ceil(65160/32)
#define NCHUNK 18

#define PITCH      224
#define A_TILE     (XYT * PITCH)         // 7168
#define ABUF       (4 * A_TILE)          // 28672
#define OHALF      48
#define W_TILE     (OHALF * PITCH)       // 10752
#define SM_A       1024
#define SM_W       (SM_A + 2 * ABUF)     // 58368
#define SMEM_TOTAL (SM_W + 4 * W_TILE)   // 101376  (x2 CTAs = 202752)

static __device__ __forceinline__ void split2(float a, float b, uint32_t& hi, uint32_t& lo) {
    uint32_t ua = __float_as_uint(a), ub = __float_as_uint(b);
    asm("prmt.b32 %0, %1, %2, 0x7632;" : "=r"(hi) : "r"(ua), "r"(ub));
    float ra = a - __uint_as_float(ua & 0xFFFF0000u);
    float rb = b - __uint_as_float(ub & 0xFFFF0000u);
    asm("cvt.rn.bf16x2.f32 %0, %1, %2;" : "=r"(lo) : "f"(rb), "f"(ra));
}
static __device__ __forceinline__ int kword(int j) {
    return ((j >> 3) << 3) + ((j & 3) << 1) + ((j >> 2) & 1);
}
static __device__ __forceinline__ uint32_t smem_u32(const void* p) {
    uint32_t a;
    asm("{ .reg .u64 t; cvta.to.shared.u64 t, %1; cvt.u32.u64 %0, t; }" : "=r"(a) : "l"(p));
    return a;
}
static __device__ __forceinline__ void mbar_wait(uint32_t addr, int parity) {
    asm volatile(
        "{ .reg .pred P;\n\t"
        "WL%=: mbarrier.try_wait.parity.acquire.cta.shared::cta.b64 P, [%0], %1, 0x989680;\n\t"
        "@P bra WD%=;\n\t"
        "bra WL%=;\n\t"
        "WD%=: }"
        :: "r"(addr), "r"((uint32_t)parity) : "memory");
}
static __device__ __forceinline__ void mbar_arrive(uint32_t addr) {
    asm volatile("mbarrier.arrive.shared.b64 _, [%0];" :: "r"(addr) : "memory");
}

#define MMA(c, a, b)                                                            \
    asm volatile("mma.sync.aligned.m16n8k16.row.col.f32.bf16.bf16.f32 "         \
        "{%0,%1,%2,%3},{%4,%5,%6,%7},{%8,%9},{%0,%1,%2,%3};"                    \
        : "+f"((c)[0]), "+f"((c)[1]), "+f"((c)[2]), "+f"((c)[3])                \
        : "r"((a)[0]), "r"((a)[1]), "r"((a)[2]), "r"((a)[3]),                   \
          "r"((b).x), "r"((b).y))

// unit u (0..191): p = u/12 (xy-pair 0..15), h = u%12 -> b = h>>1 (16-i block), f = h&1
static __device__ __forceinline__ void prod_load(float4* v, const float4* s4, int u, int xy0) {
    const int p = u / 12, h = u % 12, b = h >> 1, f = h & 1;
    const int i0 = b * 16 + f * 4;
    const bool ok = (xy0 + 2 * p) < XYTOT;
    const size_t g4 = (size_t)(xy0 >> 1) + p;
    #pragma unroll
    for (int q = 0; q < 4; ++q) {
        v[q]     = ok ? __ldg(&s4[(size_t)(i0 + q)     * XYH + g4]) : make_float4(0.f,0.f,0.f,0.f);
        v[4 + q] = ok ? __ldg(&s4[(size_t)(i0 + 8 + q) * XYH + g4]) : make_float4(0.f,0.f,0.f,0.f);
    }
}
static __device__ __forceinline__ void prod_store(unsigned char* sm, const float4* v,
                                                  int u, uint32_t abase) {
    const int p = u / 12, h = u % 12, b = h >> 1, f = h & 1;
    const uint32_t chunk = (uint32_t)(b * 32 + f * 16);
    uint4 RH, RL, IH, IL;
    split2(v[0].x, v[1].x, RH.x, RL.x);  split2(v[4].x, v[5].x, RH.y, RL.y);
    split2(v[2].x, v[3].x, RH.z, RL.z);  split2(v[6].x, v[7].x, RH.w, RL.w);
    split2(v[0].y, v[1].y, IH.x, IL.x);  split2(v[4].y, v[5].y, IH.y, IL.y);
    split2(v[2].y, v[3].y, IH.z, IL.z);  split2(v[6].y, v[7].y, IH.w, IL.w);
    uint32_t off = abase + (uint32_t)(2 * p) * PITCH + chunk;
    *(uint4*)(sm + off + 0 * A_TILE) = RH;
    *(uint4*)(sm + off + 1 * A_TILE) = RL;
    *(uint4*)(sm + off + 2 * A_TILE) = IH;
    *(uint4*)(sm + off + 3 * A_TILE) = IL;
    split2(v[0].z, v[1].z, RH.x, RL.x);  split2(v[4].z, v[5].z, RH.y, RL.y);
    split2(v[2].z, v[3].z, RH.z, RL.z);  split2(v[6].z, v[7].z, RH.w, RL.w);
    split2(v[0].w, v[1].w, IH.x, IL.x);  split2(v[4].w, v[5].w, IH.y, IL.y);
    split2(v[2].w, v[3].w, IH.z, IL.z);  split2(v[6].w, v[7].w, IH.w, IL.w);
    off += PITCH;
    *(uint4*)(sm + off + 0 * A_TILE) = RH;
    *(uint4*)(sm + off + 1 * A_TILE) = RL;
    *(uint4*)(sm + off + 2 * A_TILE) = IH;
    *(uint4*)(sm + off + 3 * A_TILE) = IL;
}

__global__ __launch_bounds__(NTHR, 2)
void cmul_2c(const float2* __restrict__ inp, const float2* __restrict__ wgt,
             const float2* __restrict__ bias, float2* __restrict__ out)
{
    extern __shared__ unsigned char sm[];
    const uint32_t smb = smem_u32(sm);
    const int tid = threadIdx.x, lane = tid & 31, wid = tid >> 5;
    const int kk = blockIdx.y;
    const int chunk = blockIdx.x >> 1;       // xy chunk 0..17
    const int oh    = blockIdx.x & 1;        // o half 0..1

    const int basecnt = NTILES / NCHUNK;             // 113
    const int rem     = NTILES - basecnt * NCHUNK;   // 3
    const int cnt     = basecnt + (chunk < rem ? 1 : 0);
    const int t0      = chunk * basecnt + (chunk < rem ? chunk : rem);

    if (tid == 0) {
        asm volatile("mbarrier.init.shared.b64 [%0], %1;" :: "r"(smb + 0),  "r"(64u)  : "memory");
        asm volatile("mbarrier.init.shared.b64 [%0], %1;" :: "r"(smb + 8),  "r"(64u)  : "memory");
        asm volatile("mbarrier.init.shared.b64 [%0], %1;" :: "r"(smb + 16), "r"(192u) : "memory");
        asm volatile("mbarrier.init.shared.b64 [%0], %1;" :: "r"(smb + 24), "r"(192u) : "memory");
    }

    // ---- stage W half once: Wt[o 48][i 96] -> 4 bf16 tiles ----
    for (int u = tid; u < OHALF * 48; u += NTHR) {
        const int o = u / 48, j = u % 48;
        const float2* src = wgt + (size_t)kk * IDIM * ODIM + (oh * OHALF + o);
        float2 wa = src[(size_t)(2 * j)     * ODIM];
        float2 wb = src[(size_t)(2 * j + 1) * ODIM];
        uint32_t rh, rl, ih, il;
        split2(wa.x, wb.x, rh, rl);
        split2(wa.y, wb.y, ih, il);
        const uint32_t off = (uint32_t)(o * PITCH + kword(j) * 4);
        *(uint32_t*)(sm + SM_W + 0 * W_TILE + off) = rh;
        *(uint32_t*)(sm + SM_W + 1 * W_TILE + off) = rl;
        *(uint32_t*)(sm + SM_W + 2 * W_TILE + off) = ih;
        *(uint32_t*)(sm + SM_W + 3 * W_TILE + off) = il;
    }
    __syncthreads();

    if (tid >= NCON) {
        // ================= PRODUCER (warps 6,7; 64 threads) =================
        const int ptid = tid - NCON;
        const float4* s4 = (const float4*)(inp + (size_t)kk * IDIM * XYTOT);
        int phe0 = 1, phe1 = 1;
        float4 v0[8], v1[8], v2[8];
        #pragma unroll 1
        for (int t = 0; t < cnt; ++t) {
            const int buf = t & 1;
            const int xy0 = (t0 + t) * XYT;
            const uint32_t abase = SM_A + buf * ABUF;
            prod_load(v0, s4, ptid,       xy0);
            prod_load(v1, s4, ptid + 64,  xy0);
            prod_load(v2, s4, ptid + 128, xy0);
            if (buf == 0) { mbar_wait(smb + 16, phe0); phe0 ^= 1; }
            else          { mbar_wait(smb + 24, phe1); phe1 ^= 1; }
            prod_store(sm, v0, ptid,       abase);
            prod_store(sm, v1, ptid + 64,  abase);
            prod_store(sm, v2, ptid + 128, abase);
            mbar_arrive(smb + buf * 8);  // full[buf]
        }
    } else {
        // ================= CONSUMER (warps 0-5; 192 threads) =================
        const int g = lane >> 2, tig = lane & 3;
        const int warpM = (wid & 1) * 16;       // xy offset (1 m16 tile)
        const int warpN = (wid >> 1) * 16;      // o offset within half (2 n8 tiles)

        float2 bv0[2], bv1[2];
        #pragma unroll
        for (int nt = 0; nt < 2; ++nt) {
            const int o0 = oh * OHALF + warpN + nt * 8 + 2 * tig;
            bv0[nt] = bias[kk * ODIM + o0];
            bv1[nt] = bias[kk * ODIM + o0 + 1];
        }
        float2* outk = out + (size_t)kk * ODIM * XYTOT;

        const int PA[12] = {0,1,0, 2,3,2, 2,3,2,0,1,0};
        const int PW[12] = {0,0,1, 2,2,3, 0,0,1,2,2,3};
        const int PS[12] = {0,0,0, 1,1,1, 2,2,2,2,2,2};

        int phf0 = 0, phf1 = 0;
        #pragma unroll 1
        for (int t = 0; t < cnt; ++t) {
            const int buf = t & 1;
            if (buf == 0) { mbar_wait(smb + 0, phf0); phf0 ^= 1; }
            else          { mbar_wait(smb + 8, phf1); phf1 ^= 1; }

            float acc[3][2][4];
            #pragma unroll
            for (int p = 0; p < 3; ++p)
                #pragma unroll
                for (int nt = 0; nt < 2; ++nt)
                    #pragma unroll
                    for (int q = 0; q < 4; ++q) acc[p][nt][q] = 0.f;

            const uint32_t aBase = SM_A + buf * ABUF + (uint32_t)((warpM + g) * PITCH);

            #pragma unroll 1
            for (int ks = 0; ks < 6; ++ks) {
                const uint32_t koff = (uint32_t)(ks * 32 + tig * 8);
                uint32_t Af[4][4];
                #pragma unroll
                for (int at = 0; at < 4; ++at) {
                    const uint32_t ad = aBase + at * A_TILE + koff;
                    uint2 lo = *(const uint2*)(sm + ad);
                    uint2 hi = *(const uint2*)(sm + ad + 8 * PITCH);
                    Af[at][0] = lo.x; Af[at][1] = hi.x; Af[at][2] = lo.y; Af[at][3] = hi.y;
                }
                uint2 Bf[4][2];
                #pragma unroll
                for (int wt = 0; wt < 4; ++wt)
                    #pragma unroll
                    for (int nt = 0; nt < 2; ++nt)
                        Bf[wt][nt] = *(const uint2*)(sm + SM_W + wt * W_TILE +
                                      (uint32_t)((warpN + nt * 8 + g) * PITCH) + koff);
                #pragma unroll
                for (int c = 0; c < 12; ++c)
                    #pragma unroll
                    for (int nt = 0; nt < 2; ++nt)
                        MMA(acc[PS[c]][nt], Af[PA[c]], Bf[PW[c]][nt]);
            }

            mbar_arrive(smb + 16 + buf * 8);  // empty[buf] (acc in regs)

            const int xyb = (t0 + t) * XYT + warpM;
            const int xyA = xyb + g, xyB = xyA + 8;
            const bool full = ((t0 + t) * XYT + XYT) <= XYTOT;
            #pragma unroll
            for (int nt = 0; nt < 2; ++nt) {
                const int o0 = oh * OHALF + warpN + nt * 8 + 2 * tig;
                if (full || xyA < XYTOT) {
                    outk[(size_t)o0 * XYTOT + xyA] = make_float2(
                        acc[0][nt][0] - acc[1][nt][0] + bv0[nt].x,
                        acc[2][nt][0] + bv0[nt].y);
                    outk[(size_t)(o0 + 1) * XYTOT + xyA] = make_float2(
                        acc[0][nt][1] - acc[1][nt][1] + bv1[nt].x,
                        acc[2][nt][1] + bv1[nt].y);
                }
                if (full || xyB < XYTOT) {
                    outk[(size_t)o0 * XYTOT + xyB] = make_float2(
                        acc[0][nt][2] - acc[1][nt][2] + bv0[nt].x,
                        acc[2][nt][2] + bv0[nt].y);
                    outk[(size_t)(o0 + 1) * XYTOT + xyB] = make_float2(
                        acc[0][nt][3] - acc[1][nt][3] + bv1[nt].x,
                        acc[2][nt][3] + bv1[nt].y);
                }
            }
        }
    }
}

extern "C" void kernel_launch(void* const* d_in, const int* in_sizes, int n_in,
                              void* d_out, int out_size)
{
    const float2* inp  = (const float2*)d_in[0];
    const float2* wgt  = (const float2*)d_in[1];
    const float2* bias = (const float2*)d_in[2];
    float2* out = (float2*)d_out;

    cudaFuncSetAttribute(cmul_2c, cudaFuncAttributeMaxDynamicSharedMemorySize, SMEM_TOTAL);

    dim3 grid(NCHUNK * 2, KBLK);
    cmul_2c<<<grid, NTHR, SMEM_TOTAL>>>(inp, wgt, bias, out);
}

// round 16
// speedup vs baseline: 1.5396x; 1.5396x over previous
#include <cuda_runtime.h>
#include <cuda_fp16.h>
#include <cstdint>

#define KBLK   8
#define IDIM   96
#define ODIM   96
#define XYTOT  65160
#define XYH    (XYTOT/2)
#define XYT    64
#define NTHR   320
#define NCON   256
#define NTILES 1019
#define NCHUNK 18

#define PITCH      208                   // 52 words; 52%32==20 -> conflict-free, 16B-aligned
#define A_TILE     (XYT * PITCH)         // 13312
#define ABUF       (6 * A_TILE)          // 79872
#define W_TILE     (ODIM * PITCH)        // 19968
#define SM_A       1024
#define SM_W       (SM_A + 2 * ABUF)     // 160768
#define SMEM_TOTAL (SM_W + 3 * W_TILE)   // 220672

// fp16 2-term split of two fp32 values, packed (a in low half)
static __device__ __forceinline__ void split2h(float a, float b, uint32_t& hi, uint32_t& lo) {
    __half ha = __float2half_rn(a), hb = __float2half_rn(b);
    __half2 H = __halves2half2(ha, hb);
    hi = *(uint32_t*)&H;
    float ra = a - __half2float(ha);
    float rb = b - __half2float(hb);
    asm("cvt.rn.f16x2.f32 %0, %1, %2;" : "=r"(lo) : "f"(rb), "f"(ra));  // low half = ra
}
static __device__ __forceinline__ uint32_t pack2h(float a, float b) {
    uint32_t r;
    asm("cvt.rn.f16x2.f32 %0, %1, %2;" : "=r"(r) : "f"(b), "f"(a));     // low half = a
    return r;
}
static __device__ __forceinline__ int kword(int j) {
    return ((j >> 3) << 3) + ((j & 3) << 1) + ((j >> 2) & 1);
}
static __device__ __forceinline__ uint32_t smem_u32(const void* p) {
    uint32_t a;
    asm("{ .reg .u64 t; cvta.to.shared.u64 t, %1; cvt.u32.u64 %0, t; }" : "=r"(a) : "l"(p));
    return a;
}
static __device__ __forceinline__ void mbar_wait(uint32_t addr, int parity) {
    asm volatile(
        "{ .reg .pred P;\n\t"
        "WL%=: mbarrier.try_wait.parity.acquire.cta.shared::cta.b64 P, [%0], %1, 0x989680;\n\t"
        "@P bra WD%=;\n\t"
        "bra WL%=;\n\t"
        "WD%=: }"
        :: "r"(addr), "r"((uint32_t)parity) : "memory");
}
static __device__ __forceinline__ void mbar_arrive(uint32_t addr) {
    asm volatile("mbarrier.arrive.shared.b64 _, [%0];" :: "r"(addr) : "memory");
}

#define MMA(c, a, b)                                                            \
    asm volatile("mma.sync.aligned.m16n8k16.row.col.f32.f16.f16.f32 "           \
        "{%0,%1,%2,%3},{%4,%5,%6,%7},{%8,%9},{%0,%1,%2,%3};"                    \
        : "+f"((c)[0]), "+f"((c)[1]), "+f"((c)[2]), "+f"((c)[3])                \
        : "r"((a)[0]), "r"((a)[1]), "r"((a)[2]), "r"((a)[3]),                   \
          "r"((b).x), "r"((b).y))

// unit u (0..383): p = u/12 (xy-pair), h = u%12 -> b = h>>1 (16-i block), f = h&1
static __device__ __forceinline__ void prod_load(float4* v, const float4* s4, int u, int xy0) {
    const int p = u / 12, h = u % 12, b = h >> 1, f = h & 1;
    const int i0 = b * 16 + f * 4;
    const bool ok = (xy0 + 2 * p) < XYTOT;
    const size_t g4 = (size_t)(xy0 >> 1) + p;
    #pragma unroll
    for (int q = 0; q < 4; ++q) {
        v[q]     = ok ? __ldg(&s4[(size_t)(i0 + q)     * XYH + g4]) : make_float4(0.f,0.f,0.f,0.f);
        v[4 + q] = ok ? __ldg(&s4[(size_t)(i0 + 8 + q) * XYH + g4]) : make_float4(0.f,0.f,0.f,0.f);
    }
}

// store one xy row-chunk: 6 tiles (AsH,ArH,AiH,AsL,ArL,AiL)
static __device__ __forceinline__ void store_row(unsigned char* sm, uint32_t off,
                                                 const float* ar, const float* ai) {
    uint4 SH, SL, RH, RL, IH, IL;
    float as0, as1;
    as0 = ar[0] + ai[0]; as1 = ar[1] + ai[1];  split2h(as0, as1, SH.x, SL.x);
    as0 = ar[4] + ai[4]; as1 = ar[5] + ai[5];  split2h(as0, as1, SH.y, SL.y);
    as0 = ar[2] + ai[2]; as1 = ar[3] + ai[3];  split2h(as0, as1, SH.z, SL.z);
    as0 = ar[6] + ai[6]; as1 = ar[7] + ai[7];  split2h(as0, as1, SH.w, SL.w);
    split2h(ar[0], ar[1], RH.x, RL.x);  split2h(ar[4], ar[5], RH.y, RL.y);
    split2h(ar[2], ar[3], RH.z, RL.z);  split2h(ar[6], ar[7], RH.w, RL.w);
    split2h(ai[0], ai[1], IH.x, IL.x);  split2h(ai[4], ai[5], IH.y, IL.y);
    split2h(ai[2], ai[3], IH.z, IL.z);  split2h(ai[6], ai[7], IH.w, IL.w);
    *(uint4*)(sm + off + 0 * A_TILE) = SH;
    *(uint4*)(sm + off + 1 * A_TILE) = RH;
    *(uint4*)(sm + off + 2 * A_TILE) = IH;
    *(uint4*)(sm + off + 3 * A_TILE) = SL;
    *(uint4*)(sm + off + 4 * A_TILE) = RL;
    *(uint4*)(sm + off + 5 * A_TILE) = IL;
}

static __device__ __forceinline__ void prod_store(unsigned char* sm, const float4* v,
                                                  int u, uint32_t abase) {
    const int p = u / 12, h = u % 12, b = h >> 1, f = h & 1;
    const uint32_t chunk = (uint32_t)(b * 32 + f * 16);
    const uint32_t off = abase + (uint32_t)(2 * p) * PITCH + chunk;
    float ar[8], ai[8];
    #pragma unroll
    for (int q = 0; q < 8; ++q) { ar[q] = v[q].x; ai[q] = v[q].y; }   // xy = 2p
    store_row(sm, off, ar, ai);
    #pragma unroll
    for (int q = 0; q < 8; ++q) { ar[q] = v[q].z; ai[q] = v[q].w; }   // xy = 2p+1
    store_row(sm, off + PITCH, ar, ai);
}

__global__ __launch_bounds__(NTHR, 1)
void cmul_h6(const float2* __restrict__ inp, const float2* __restrict__ wgt,
             const float2* __restrict__ bias, float2* __restrict__ out)
{
    extern __shared__ unsigned char sm[];
    const uint32_t smb = smem_u32(sm);
    const int tid = threadIdx.x, lane = tid & 31, wid = tid >> 5;
    const int kk = blockIdx.y, chunk = blockIdx.x;

    const int basecnt = NTILES / NCHUNK;
    const int rem     = NTILES - basecnt * NCHUNK;
    const int cnt     = basecnt + (chunk < rem ? 1 : 0);
    const int t0      = chunk * basecnt + (chunk < rem ? chunk : rem);

    if (tid == 0) {
        asm volatile("mbarrier.init.shared.b64 [%0], %1;" :: "r"(smb + 0),  "r"(64u)  : "memory");
        asm volatile("mbarrier.init.shared.b64 [%0], %1;" :: "r"(smb + 8),  "r"(64u)  : "memory");
        asm volatile("mbarrier.init.shared.b64 [%0], %1;" :: "r"(smb + 16), "r"(256u) : "memory");
        asm volatile("mbarrier.init.shared.b64 [%0], %1;" :: "r"(smb + 24), "r"(256u) : "memory");
    }

    // ---- stage W once: 3 fp16 tiles [Wr, Wd=Wi-Wr, Ws=Wr+Wi] ----
    for (int u = tid; u < 96 * 48; u += NTHR) {
        const int o = u / 48, j = u % 48;
        const float2* src = wgt + (size_t)kk * IDIM * ODIM + o;
        float2 wa = src[(size_t)(2 * j)     * ODIM];
        float2 wb = src[(size_t)(2 * j + 1) * ODIM];
        const uint32_t off = (uint32_t)(o * PITCH + kword(j) * 4);
        *(uint32_t*)(sm + SM_W + 0 * W_TILE + off) = pack2h(wa.x, wb.x);                  // Wr
        *(uint32_t*)(sm + SM_W + 1 * W_TILE + off) = pack2h(wa.y - wa.x, wb.y - wb.x);    // Wd
        *(uint32_t*)(sm + SM_W + 2 * W_TILE + off) = pack2h(wa.x + wa.y, wb.x + wb.y);    // Ws
    }
    __syncthreads();

    if (tid >= NCON) {
        // ================= PRODUCER (warps 8,9; 64 threads) =================
        const int ptid = tid - NCON;
        const float4* s4 = (const float4*)(inp + (size_t)kk * IDIM * XYTOT);
        int phe0 = 1, phe1 = 1;
        float4 v0[8], v1[8];
        #pragma unroll 1
        for (int t = 0; t < cnt; ++t) {
            const int buf = t & 1;
            const int xy0 = (t0 + t) * XYT;
            const uint32_t abase = SM_A + buf * ABUF;
            prod_load(v0, s4, ptid,      xy0);
            prod_load(v1, s4, ptid + 64, xy0);
            if (buf == 0) { mbar_wait(smb + 16, phe0); phe0 ^= 1; }
            else          { mbar_wait(smb + 24, phe1); phe1 ^= 1; }
            prod_store(sm, v0, ptid,       abase); prod_load(v0, s4, ptid + 128, xy0);
            prod_store(sm, v1, ptid + 64,  abase); prod_load(v1, s4, ptid + 192, xy0);
            prod_store(sm, v0, ptid + 128, abase); prod_load(v0, s4, ptid + 256, xy0);
            prod_store(sm, v1, ptid + 192, abase); prod_load(v1, s4, ptid + 320, xy0);
            prod_store(sm, v0, ptid + 256, abase);
            prod_store(sm, v1, ptid + 320, abase);
            mbar_arrive(smb + buf * 8);  // full[buf]
        }
    } else {
        // ================= CONSUMER (warps 0-7; 256 threads) =================
        const int g = lane >> 2, tig = lane & 3;
        const int warpM = (wid & 1) * 32;
        const int warpN = (wid >> 1) * 24;

        float2 bv0[3], bv1[3];
        #pragma unroll
        for (int nt = 0; nt < 3; ++nt) {
            const int o0 = warpN + nt * 8 + 2 * tig;
            bv0[nt] = bias[kk * ODIM + o0];
            bv1[nt] = bias[kk * ODIM + o0 + 1];
        }
        float2* outk = out + (size_t)kk * ODIM * XYTOT;

        int phf0 = 0, phf1 = 0;
        #pragma unroll 1
        for (int t = 0; t < cnt; ++t) {
            const int buf = t & 1;
            if (buf == 0) { mbar_wait(smb + 0, phf0); phf0 ^= 1; }
            else          { mbar_wait(smb + 8, phf1); phf1 ^= 1; }

            float acc[3][2][3][4];     // [m1,m2,m3][mt][nt][quad]
            #pragma unroll
            for (int p = 0; p < 3; ++p)
                #pragma unroll
                for (int mt = 0; mt < 2; ++mt)
                    #pragma unroll
                    for (int nt = 0; nt < 3; ++nt)
                        #pragma unroll
                        for (int q = 0; q < 4; ++q) acc[p][mt][nt][q] = 0.f;

            const uint32_t aBase = SM_A + buf * ABUF + (uint32_t)((warpM + g) * PITCH);

            #pragma unroll 1
            for (int ks = 0; ks < 6; ++ks) {
                const uint32_t koff = (uint32_t)(ks * 32 + tig * 8);
                uint32_t Af[6][2][4];
                #pragma unroll
                for (int at = 0; at < 6; ++at)
                    #pragma unroll
                    for (int mt = 0; mt < 2; ++mt) {
                        const uint32_t ad = aBase + at * A_TILE + mt * (16 * PITCH) + koff;
                        uint2 lo = *(const uint2*)(sm + ad);
                        uint2 hi = *(const uint2*)(sm + ad + 8 * PITCH);
                        Af[at][mt][0] = lo.x; Af[at][mt][1] = hi.x;
                        Af[at][mt][2] = lo.y; Af[at][mt][3] = hi.y;
                    }
                uint2 Bf[3][3];
                #pragma unroll
                for (int wt = 0; wt < 3; ++wt)
                    #pragma unroll
                    for (int nt = 0; nt < 3; ++nt)
                        Bf[wt][nt] = *(const uint2*)(sm + SM_W + wt * W_TILE +
                                      (uint32_t)((warpN + nt * 8 + g) * PITCH) + koff);
                // 6 passes: s=0 A-hi, s=1 A-lo; p: 0=(As,Wr) 1=(Ar,Wd) 2=(Ai,Ws)
                #pragma unroll
                for (int s = 0; s < 2; ++s)
                    #pragma unroll
                    for (int p = 0; p < 3; ++p)
                        #pragma unroll
                        for (int nt = 0; nt < 3; ++nt)
                            #pragma unroll
                            for (int mt = 0; mt < 2; ++mt)
                                MMA(acc[p][mt][nt], Af[s * 3 + p][mt], Bf[p][nt]);
            }

            mbar_arrive(smb + 16 + buf * 8);  // empty[buf] (acc in regs)

            // epilogue: re = m1 - m3 + br ; im = m1 + m2 + bi
            const int xyb = (t0 + t) * XYT + warpM;
            const bool full = ((t0 + t) * XYT + XYT) <= XYTOT;
            #pragma unroll
            for (int nt = 0; nt < 3; ++nt) {
                const int o0 = warpN + nt * 8 + 2 * tig;
                #pragma unroll
                for (int mt = 0; mt < 2; ++mt) {
                    const int xyA = xyb + mt * 16 + g;
                    const int xyB = xyA + 8;
                    if (full || xyA < XYTOT) {
                        outk[(size_t)o0 * XYTOT + xyA] = make_float2(
                            acc[0][mt][nt][0] - acc[2][mt][nt][0] + bv0[nt].x,
                            acc[0][mt][nt][0] + acc[1][mt][nt][0] + bv0[nt].y);
                        outk[(size_t)(o0 + 1) * XYTOT + xyA] = make_float2(
                            acc[0][mt][nt][1] - acc[2][mt][nt][1] + bv1[nt].x,
                            acc[0][mt][nt][1] + acc[1][mt][nt][1] + bv1[nt].y);
                    }
                    if (full || xyB < XYTOT) {
                        outk[(size_t)o0 * XYTOT + xyB] = make_float2(
                            acc[0][mt][nt][2] - acc[2][mt][nt][2] + bv0[nt].x,
                            acc[0][mt][nt][2] + acc[1][mt][nt][2] + bv0[nt].y);
                        outk[(size_t)(o0 + 1) * XYTOT + xyB] = make_float2(
                            acc[0][mt][nt][3] - acc[2][mt][nt][3] + bv1[nt].x,
                            acc[0][mt][nt][3] + acc[1][mt][nt][3] + bv1[nt].y);
                    }
                }
            }
        }
    }
}

extern "C" void kernel_launch(void* const* d_in, const int* in_sizes, int n_in,
                              void* d_out, int out_size)
{
    const float2* inp  = (const float2*)d_in[0];
    const float2* wgt  = (const float2*)d_in[1];
    const float2* bias = (const float2*)d_in[2];
    float2* out = (float2*)d_out;

    cudaFuncSetAttribute(cmul_h6, cudaFuncAttributeMaxDynamicSharedMemorySize, SMEM_TOTAL);

    dim3 grid(NCHUNK, KBLK);
    cmul_h6<<<grid, NTHR, SMEM_TOTAL>>>(inp, wgt, bias, out);
}